// round 1
// baseline (speedup 1.0000x reference)
#include <cuda_runtime.h>

#define N_NODES 163842
#define N_EDGES 983040

// ---------------- scratch (device globals; no allocation allowed) ----------------
__device__ float d_xw[(size_t)N_NODES * 256];   // x @ [g | root], M = 4*Cout (<=256)
__device__ float d_agg[(size_t)N_NODES * 64];
__device__ float d_h0[(size_t)N_NODES * 64];
__device__ float d_h1[(size_t)N_NODES * 64];
__device__ float d_gauss[(size_t)N_EDGES * 3];
__device__ float d_deg[N_NODES];
__device__ int   d_src[N_EDGES];
__device__ int   d_dst[N_EDGES];
__device__ int   d_is64;

// ---------------- misc kernels ----------------
__global__ void zero_kernel(float* p, int n) {
    int i = blockIdx.x * blockDim.x + threadIdx.x;
    if (i < n) p[i] = 0.f;
}

// Detect whether edge_index is int64 or int32: node ids < 2^18, so for int64
// every odd 32-bit word (high half) is zero. For uniform int32 node ids the
// chance all 32 sampled odd words are zero is negligible.
__global__ void detect_kernel(const unsigned* ei) {
    if (blockIdx.x == 0 && threadIdx.x == 0) {
        int ok = 1;
        for (int i = 1; i < 64; i += 2)
            if (ei[i] != 0u) ok = 0;
        d_is64 = ok;
    }
}

__global__ void convert_edges(const void* eiv) {
    int e = blockIdx.x * blockDim.x + threadIdx.x;
    if (e >= N_EDGES) return;
    if (d_is64) {
        const long long* ei = (const long long*)eiv;
        d_src[e] = (int)ei[e];
        d_dst[e] = (int)ei[N_EDGES + e];
    } else {
        const int* ei = (const int*)eiv;
        d_src[e] = ei[e];
        d_dst[e] = ei[N_EDGES + e];
    }
}

__global__ void deg_kernel() {
    int e = blockIdx.x * blockDim.x + threadIdx.x;
    if (e < N_EDGES) atomicAdd(&d_deg[d_dst[e]], 1.0f);
}

// Per-edge Gaussian kernel weights for one layer: [E, 3]
__global__ void gauss_kernel(const float* __restrict__ ea,
                             const float* __restrict__ mu,
                             const float* __restrict__ sigma) {
    int e = blockIdx.x * blockDim.x + threadIdx.x;
    if (e >= N_EDGES) return;
    float p0 = ea[2 * e], p1 = ea[2 * e + 1];
#pragma unroll
    for (int k = 0; k < 3; k++) {
        float dd0 = p0 - mu[2 * k];
        float dd1 = p1 - mu[2 * k + 1];
        float s0 = sigma[2 * k], s1 = sigma[2 * k + 1];
        float q = dd0 * dd0 / (1e-15f + s0 * s0) + dd1 * dd1 / (1e-15f + s1 * s1);
        d_gauss[3 * e + k] = expf(-0.5f * q);
    }
}

// ---------------- register-tiled GEMM: xw[n, 0:3C] = x@g, xw[n, 3C:4C] = x@root ----
// M = 4*COUT = BX*TM.  Block: (BX, 4) threads, BN = 16 nodes per block.
template <int CIN, int CC, int COUT, int BX, int TM, int TN, int BN>
__global__ void gemm_kernel(const float* __restrict__ x,
                            const float* __restrict__ g,
                            const float* __restrict__ root,
                            float* __restrict__ xw) {
    constexpr int M = BX * TM;
    constexpr int KM = 3 * COUT;
    __shared__ float gs[CC * M];
    __shared__ float xs[BN * CIN];
    const int tid = threadIdx.y * BX + threadIdx.x;
    const int NT = BX * 4;
    const int n0 = blockIdx.x * BN;

    for (int i = tid; i < BN * CIN; i += NT) {
        int nn = i / CIN, cc = i - nn * CIN;
        int n = n0 + nn;
        xs[i] = (n < N_NODES) ? x[(size_t)n * CIN + cc] : 0.f;
    }

    float acc[TN][TM];
#pragma unroll
    for (int j = 0; j < TN; j++)
#pragma unroll
        for (int i = 0; i < TM; i++) acc[j][i] = 0.f;

    const int nb = threadIdx.y * TN;
    for (int c0 = 0; c0 < CIN; c0 += CC) {
        __syncthreads();
        for (int i = tid; i < CC * M; i += NT) {
            int r = i / M, col = i - r * M;
            int gc = c0 + r;
            gs[i] = (col < KM) ? g[gc * KM + col] : root[gc * COUT + (col - KM)];
        }
        __syncthreads();
#pragma unroll
        for (int c = 0; c < CC; c++) {
            float gv[TM], xv[TN];
#pragma unroll
            for (int i = 0; i < TM; i++) gv[i] = gs[c * M + threadIdx.x + i * BX];
#pragma unroll
            for (int j = 0; j < TN; j++) xv[j] = xs[(nb + j) * CIN + c0 + c];
#pragma unroll
            for (int j = 0; j < TN; j++)
#pragma unroll
                for (int i = 0; i < TM; i++) acc[j][i] += xv[j] * gv[i];
        }
    }

#pragma unroll
    for (int j = 0; j < TN; j++) {
        int n = n0 + nb + j;
        if (n >= N_NODES) continue;
#pragma unroll
        for (int i = 0; i < TM; i++)
            xw[(size_t)n * M + threadIdx.x + i * BX] = acc[j][i];
    }
}

// ---------------- edge scatter: agg[dst] += sum_k gauss[e,k]*xw[src,k,:] ----------
template <int COUT>
__global__ void scatter_kernel(const float* __restrict__ xw) {
    constexpr int M = 4 * COUT;
    unsigned idx = blockIdx.x * blockDim.x + threadIdx.x;
    unsigned e = idx / COUT;
    int o = idx - e * COUT;
    if (e >= N_EDGES) return;
    int src = d_src[e], dst = d_dst[e];
    float g0 = d_gauss[3 * e], g1 = d_gauss[3 * e + 1], g2 = d_gauss[3 * e + 2];
    const float* p = xw + (size_t)src * M;
    float m = g0 * p[o] + g1 * p[COUT + o] + g2 * p[2 * COUT + o];
    atomicAdd(&d_agg[(size_t)dst * COUT + o], m);
}

// ---------------- combine: relu(agg/deg + x@root + b) ----------------------------
template <int COUT>
__global__ void combine_kernel(const float* __restrict__ xw,
                               const float* __restrict__ bias,
                               float* __restrict__ out) {
    constexpr int M = 4 * COUT;
    int idx = blockIdx.x * blockDim.x + threadIdx.x;
    if (idx >= N_NODES * COUT) return;
    int n = idx / COUT, o = idx - n * COUT;
    float a = d_agg[idx] / fmaxf(d_deg[n], 1.f)
            + xw[(size_t)n * M + 3 * COUT + o] + bias[o];
    out[idx] = fmaxf(a, 0.f);
}

// ---------------- fc + log_softmax (2 classes) ------------------------------------
__global__ void final_kernel(const float* __restrict__ h,
                             const float* __restrict__ w,
                             const float* __restrict__ b,
                             float* __restrict__ out) {
    int n = blockIdx.x * blockDim.x + threadIdx.x;
    if (n >= N_NODES) return;
    float l0 = b[0], l1 = b[1];
    const float4* h4 = (const float4*)(h + (size_t)n * 64);
#pragma unroll
    for (int i = 0; i < 16; i++) {
        float4 v = h4[i];
        int c = 4 * i;
        l0 += v.x * w[2 * c] + v.y * w[2 * (c + 1)] + v.z * w[2 * (c + 2)] + v.w * w[2 * (c + 3)];
        l1 += v.x * w[2 * c + 1] + v.y * w[2 * (c + 1) + 1] + v.z * w[2 * (c + 2) + 1] + v.w * w[2 * (c + 3) + 1];
    }
    float mx = fmaxf(l0, l1);
    float lse = mx + logf(expf(l0 - mx) + expf(l1 - mx));
    out[2 * n] = l0 - lse;
    out[2 * n + 1] = l1 - lse;
}

// ---------------- launch ----------------------------------------------------------
extern "C" void kernel_launch(void* const* d_in, const int* in_sizes, int n_in,
                              void* d_out, int out_size) {
    const float* x   = (const float*)d_in[0];
    const void*  ei  = d_in[1];
    const float* ea  = (const float*)d_in[2];
    const float* g[3]  = {(const float*)d_in[3],  (const float*)d_in[8],  (const float*)d_in[13]};
    const float* mu[3] = {(const float*)d_in[4],  (const float*)d_in[9],  (const float*)d_in[14]};
    const float* sg[3] = {(const float*)d_in[5],  (const float*)d_in[10], (const float*)d_in[15]};
    const float* rt[3] = {(const float*)d_in[6],  (const float*)d_in[11], (const float*)d_in[16]};
    const float* bi[3] = {(const float*)d_in[7],  (const float*)d_in[12], (const float*)d_in[17]};
    const float* fcw = (const float*)d_in[18];
    const float* fcb = (const float*)d_in[19];
    float* out = (float*)d_out;

    float *xw, *agg, *h0, *h1, *deg;
    cudaGetSymbolAddress((void**)&xw,  d_xw);
    cudaGetSymbolAddress((void**)&agg, d_agg);
    cudaGetSymbolAddress((void**)&h0,  d_h0);
    cudaGetSymbolAddress((void**)&h1,  d_h1);
    cudaGetSymbolAddress((void**)&deg, d_deg);

    const int EB = (N_EDGES + 255) / 256;

    detect_kernel<<<1, 32>>>((const unsigned*)ei);
    convert_edges<<<EB, 256>>>(ei);
    zero_kernel<<<(N_NODES + 255) / 256, 256>>>(deg, N_NODES);
    deg_kernel<<<EB, 256>>>();

    // ---- layer 0: 22 -> 32 ----
    gauss_kernel<<<EB, 256>>>(ea, mu[0], sg[0]);
    gemm_kernel<22, 22, 32, 32, 4, 4, 16>
        <<<(N_NODES + 15) / 16, dim3(32, 4)>>>(x, g[0], rt[0], xw);
    zero_kernel<<<(N_NODES * 32 + 255) / 256, 256>>>(agg, N_NODES * 32);
    scatter_kernel<32><<<(unsigned)(((size_t)N_EDGES * 32 + 255) / 256), 256>>>(xw);
    combine_kernel<32><<<(N_NODES * 32 + 255) / 256, 256>>>(xw, bi[0], h0);

    // ---- layer 1: 32 -> 64 ----
    gauss_kernel<<<EB, 256>>>(ea, mu[1], sg[1]);
    gemm_kernel<32, 32, 64, 64, 4, 4, 16>
        <<<(N_NODES + 15) / 16, dim3(64, 4)>>>(h0, g[1], rt[1], xw);
    zero_kernel<<<(N_NODES * 64 + 255) / 256, 256>>>(agg, N_NODES * 64);
    scatter_kernel<64><<<(unsigned)(((size_t)N_EDGES * 64 + 255) / 256), 256>>>(xw);
    combine_kernel<64><<<(N_NODES * 64 + 255) / 256, 256>>>(xw, bi[1], h1);

    // ---- layer 2: 64 -> 64 ----
    gauss_kernel<<<EB, 256>>>(ea, mu[2], sg[2]);
    gemm_kernel<64, 32, 64, 64, 4, 4, 16>
        <<<(N_NODES + 15) / 16, dim3(64, 4)>>>(h1, g[2], rt[2], xw);
    zero_kernel<<<(N_NODES * 64 + 255) / 256, 256>>>(agg, N_NODES * 64);
    scatter_kernel<64><<<(unsigned)(((size_t)N_EDGES * 64 + 255) / 256), 256>>>(xw);
    combine_kernel<64><<<(N_NODES * 64 + 255) / 256, 256>>>(xw, bi[2], h0);

    final_kernel<<<(N_NODES + 127) / 128, 128>>>(h0, fcw, fcb, out);
}

// round 2
// speedup vs baseline: 1.8136x; 1.8136x over previous
#include <cuda_runtime.h>

#define N_NODES 163842
#define N_EDGES 983040
#define SCAN_B  1024
#define SCAN_NB ((N_NODES + SCAN_B - 1) / SCAN_B)   // 161

// ---------------- scratch (device globals; no allocation allowed) ----------------
__device__ float d_xwm[(size_t)N_NODES * 192];   // x @ g   (3*Cout, dense rows)
__device__ float d_xwr[(size_t)N_NODES * 64];    // x @ root
__device__ float d_h0[(size_t)N_NODES * 64];
__device__ float d_h1[(size_t)N_NODES * 64];
__device__ float d_gauss[(size_t)N_EDGES * 3];   // per-edge kernel weights, CSR order
__device__ float2 d_csr_ea[N_EDGES];             // pseudo-coords, CSR order
__device__ int   d_csr_src[N_EDGES];
__device__ int   d_src[N_EDGES];
__device__ int   d_dst[N_EDGES];
__device__ int   d_cnt[N_NODES];
__device__ int   d_incl[N_NODES];
__device__ int   d_rowptr[N_NODES + 1];
__device__ int   d_cursor[N_NODES];
__device__ int   d_bsum[SCAN_NB];
__device__ int   d_is64;

// ---------------- edge index handling ----------------
__global__ void detect_kernel(const unsigned* ei) {
    if (threadIdx.x == 0) {
        int ok = 1;
        for (int i = 1; i < 64; i += 2)
            if (ei[i] != 0u) ok = 0;
        d_is64 = ok;
    }
}

__global__ void convert_edges(const void* eiv) {
    int e = blockIdx.x * blockDim.x + threadIdx.x;
    if (e >= N_EDGES) return;
    if (d_is64) {
        const long long* ei = (const long long*)eiv;
        d_src[e] = (int)ei[e];
        d_dst[e] = (int)ei[N_EDGES + e];
    } else {
        const int* ei = (const int*)eiv;
        d_src[e] = ei[e];
        d_dst[e] = ei[N_EDGES + e];
    }
}

// ---------------- CSR build ----------------
__global__ void zero_cnt() {
    int i = blockIdx.x * blockDim.x + threadIdx.x;
    if (i < N_NODES) d_cnt[i] = 0;
}

__global__ void hist_kernel() {
    int e = blockIdx.x * blockDim.x + threadIdx.x;
    if (e < N_EDGES) atomicAdd(&d_cnt[d_dst[e]], 1);
}

__global__ void scan1() {
    __shared__ int s[2][SCAN_B];
    int t = threadIdx.x;
    int i = blockIdx.x * SCAN_B + t;
    int v = (i < N_NODES) ? d_cnt[i] : 0;
    s[0][t] = v;
    int cur = 0;
    for (int off = 1; off < SCAN_B; off <<= 1) {
        __syncthreads();
        int nv = s[cur][t] + (t >= off ? s[cur][t - off] : 0);
        s[cur ^ 1][t] = nv;
        cur ^= 1;
    }
    __syncthreads();
    if (i < N_NODES) d_incl[i] = s[cur][t];
    if (t == SCAN_B - 1) d_bsum[blockIdx.x] = s[cur][t];
}

__global__ void scan2() {
    if (threadIdx.x == 0) {
        int run = 0;
        for (int b = 0; b < SCAN_NB; b++) {
            int t = d_bsum[b];
            d_bsum[b] = run;
            run += t;
        }
        d_rowptr[N_NODES] = run;   // == N_EDGES
    }
}

__global__ void scan3() {
    int i = blockIdx.x * blockDim.x + threadIdx.x;
    if (i >= N_NODES) return;
    int excl = d_incl[i] - d_cnt[i] + d_bsum[i / SCAN_B];
    d_rowptr[i] = excl;
    d_cursor[i] = excl;
}

__global__ void fill_kernel(const float* __restrict__ ea) {
    int e = blockIdx.x * blockDim.x + threadIdx.x;
    if (e >= N_EDGES) return;
    int p = atomicAdd(&d_cursor[d_dst[e]], 1);
    d_csr_src[p] = d_src[e];
    d_csr_ea[p] = ((const float2*)ea)[e];
}

// ---------------- Gaussian weights (CSR order) ----------------
__global__ void gauss_csr(const float* __restrict__ mu,
                          const float* __restrict__ sigma) {
    int i = blockIdx.x * blockDim.x + threadIdx.x;
    if (i >= N_EDGES) return;
    float2 pc = d_csr_ea[i];
#pragma unroll
    for (int k = 0; k < 3; k++) {
        float dd0 = pc.x - mu[2 * k];
        float dd1 = pc.y - mu[2 * k + 1];
        float s0 = sigma[2 * k], s1 = sigma[2 * k + 1];
        float q = dd0 * dd0 / (1e-15f + s0 * s0) + dd1 * dd1 / (1e-15f + s1 * s1);
        d_gauss[3 * i + k] = __expf(-0.5f * q);
    }
}

// ---------------- GEMM (layer 0): M=128 = [96 msg | 32 root], K=22, scalar tile --
template <int CIN, int COUT, int BX, int TM, int TN, int BN>
__global__ void gemm_s(const float* __restrict__ x,
                       const float* __restrict__ g,
                       const float* __restrict__ root,
                       float* __restrict__ xwm, float* __restrict__ xwr) {
    constexpr int M = BX * TM;
    constexpr int KM = 3 * COUT;
    __shared__ float gs[CIN * M];
    __shared__ float xs[BN * CIN];
    const int tid = threadIdx.y * BX + threadIdx.x;
    const int NT = BX * 4;
    const int n0 = blockIdx.x * BN;

    for (int i = tid; i < BN * CIN; i += NT) {
        int gi = n0 * CIN + i;
        xs[i] = (gi < N_NODES * CIN) ? x[gi] : 0.f;
    }
    for (int i = tid; i < CIN * M; i += NT) {
        int r = i / M, col = i - r * M;
        gs[i] = (col < KM) ? g[r * KM + col] : root[r * COUT + (col - KM)];
    }
    __syncthreads();

    float acc[TN][TM];
#pragma unroll
    for (int j = 0; j < TN; j++)
#pragma unroll
        for (int i = 0; i < TM; i++) acc[j][i] = 0.f;

    const int nb = threadIdx.y * TN;
#pragma unroll
    for (int c = 0; c < CIN; c++) {
        float gv[TM], xv[TN];
#pragma unroll
        for (int i = 0; i < TM; i++) gv[i] = gs[c * M + threadIdx.x + i * BX];
#pragma unroll
        for (int j = 0; j < TN; j++) xv[j] = xs[(nb + j) * CIN + c];
#pragma unroll
        for (int j = 0; j < TN; j++)
#pragma unroll
            for (int i = 0; i < TM; i++) acc[j][i] += xv[j] * gv[i];
    }

#pragma unroll
    for (int j = 0; j < TN; j++) {
        int n = n0 + nb + j;
        if (n >= N_NODES) continue;
#pragma unroll
        for (int i = 0; i < TM; i++) {
            int col = threadIdx.x + i * BX;
            if (col < KM) xwm[(size_t)n * KM + col] = acc[j][i];
            else          xwr[(size_t)n * COUT + (col - KM)] = acc[j][i];
        }
    }
}

// ---------------- GEMM (layers 1/2): M=256 = [192 msg | 64 root], vectorized -----
template <int CIN, int CC, int TN>
__global__ void gemm_vec(const float* __restrict__ x,
                         const float* __restrict__ g,
                         const float* __restrict__ root,
                         float* __restrict__ xwm, float* __restrict__ xwr) {
    constexpr int M = 256, KM = 192, COUT = 64, BX = 32, BY = 8;
    constexpr int BN = BY * TN;
    __shared__ __align__(16) float gs[CC * M];
    __shared__ __align__(16) float xs[BN * CIN];
    const int tx = threadIdx.x, ty = threadIdx.y;
    const int tid = ty * BX + tx;
    constexpr int NT = BX * BY;
    const int n0 = blockIdx.x * BN;

    for (int i = tid; i < BN * CIN; i += NT) {
        int gi = n0 * CIN + i;
        xs[i] = (gi < N_NODES * CIN) ? x[gi] : 0.f;
    }

    float acc[TN][8];
#pragma unroll
    for (int j = 0; j < TN; j++)
#pragma unroll
        for (int i = 0; i < 8; i++) acc[j][i] = 0.f;

    const int nb = ty * TN;
    for (int c0 = 0; c0 < CIN; c0 += CC) {
        __syncthreads();
        for (int i = tid; i < CC * M; i += NT) {
            int r = i / M, col = i - r * M;
            int gr = c0 + r;
            gs[i] = (col < KM) ? g[gr * KM + col] : root[gr * COUT + (col - KM)];
        }
        __syncthreads();
#pragma unroll
        for (int c4 = 0; c4 < CC; c4 += 4) {
            float4 xv[TN];
#pragma unroll
            for (int j = 0; j < TN; j++)
                xv[j] = *(const float4*)&xs[(nb + j) * CIN + c0 + c4];
#pragma unroll
            for (int q = 0; q < 4; q++) {
                float4 ga = *(const float4*)&gs[(c4 + q) * M + tx * 4];
                float4 gb = *(const float4*)&gs[(c4 + q) * M + 128 + tx * 4];
#pragma unroll
                for (int j = 0; j < TN; j++) {
                    float xc = ((const float*)&xv[j])[q];
                    acc[j][0] += xc * ga.x; acc[j][1] += xc * ga.y;
                    acc[j][2] += xc * ga.z; acc[j][3] += xc * ga.w;
                    acc[j][4] += xc * gb.x; acc[j][5] += xc * gb.y;
                    acc[j][6] += xc * gb.z; acc[j][7] += xc * gb.w;
                }
            }
        }
    }

#pragma unroll
    for (int j = 0; j < TN; j++) {
        int n = n0 + nb + j;
        if (n >= N_NODES) continue;
        // chunk 0: cols [tx*4, tx*4+4)  -> always msg (0..127 < 192)
        *(float4*)&xwm[(size_t)n * KM + tx * 4] =
            make_float4(acc[j][0], acc[j][1], acc[j][2], acc[j][3]);
        // chunk 1: cols [128+tx*4, 128+tx*4+4)
        int col = 128 + tx * 4;
        float4 v = make_float4(acc[j][4], acc[j][5], acc[j][6], acc[j][7]);
        if (col < KM) *(float4*)&xwm[(size_t)n * KM + col] = v;
        else          *(float4*)&xwr[(size_t)n * COUT + (col - KM)] = v;
    }
}

// ---------------- gather + combine, Cout=32 (layer 0) ----------------
__global__ void gather32(const float* __restrict__ xwm,
                         const float* __restrict__ xwr,
                         const float* __restrict__ bias,
                         float* __restrict__ out) {
    int warp = (blockIdx.x * blockDim.x + threadIdx.x) >> 5;
    int lane = threadIdx.x & 31;
    if (warp >= N_NODES) return;
    int beg = d_rowptr[warp], end = d_rowptr[warp + 1];
    float a0 = 0.f;
    for (int i = beg; i < end; i++) {
        int s = d_csr_src[i];
        float g0 = d_gauss[3 * i], g1 = d_gauss[3 * i + 1], g2 = d_gauss[3 * i + 2];
        const float* p = xwm + (size_t)s * 96;
        a0 += g0 * p[lane] + g1 * p[32 + lane] + g2 * p[64 + lane];
    }
    float inv = 1.f / fmaxf((float)(end - beg), 1.f);
    float h = a0 * inv + xwr[(size_t)warp * 32 + lane] + bias[lane];
    out[(size_t)warp * 32 + lane] = fmaxf(h, 0.f);
}

// ---------------- gather + combine, Cout=64 (layers 1/2; layer2 fuses FC) -------
template <bool FINAL>
__global__ void gather64(const float* __restrict__ xwm,
                         const float* __restrict__ xwr,
                         const float* __restrict__ bias,
                         const float* __restrict__ fcw,
                         const float* __restrict__ fcb,
                         float* __restrict__ out) {
    int warp = (blockIdx.x * blockDim.x + threadIdx.x) >> 5;
    int lane = threadIdx.x & 31;
    if (warp >= N_NODES) return;
    int beg = d_rowptr[warp], end = d_rowptr[warp + 1];
    float a0 = 0.f, a1 = 0.f;
    for (int i = beg; i < end; i++) {
        int s = d_csr_src[i];
        float g0 = d_gauss[3 * i], g1 = d_gauss[3 * i + 1], g2 = d_gauss[3 * i + 2];
        const float* p = xwm + (size_t)s * 192;
        a0 += g0 * p[lane]      + g1 * p[64 + lane]  + g2 * p[128 + lane];
        a1 += g0 * p[32 + lane] + g1 * p[96 + lane]  + g2 * p[160 + lane];
    }
    float inv = 1.f / fmaxf((float)(end - beg), 1.f);
    float h0 = fmaxf(a0 * inv + xwr[(size_t)warp * 64 + lane]      + bias[lane], 0.f);
    float h1 = fmaxf(a1 * inv + xwr[(size_t)warp * 64 + 32 + lane] + bias[32 + lane], 0.f);
    if (!FINAL) {
        out[(size_t)warp * 64 + lane] = h0;
        out[(size_t)warp * 64 + 32 + lane] = h1;
    } else {
        float p0 = h0 * fcw[2 * lane]     + h1 * fcw[2 * (lane + 32)];
        float p1 = h0 * fcw[2 * lane + 1] + h1 * fcw[2 * (lane + 32) + 1];
#pragma unroll
        for (int off = 16; off > 0; off >>= 1) {
            p0 += __shfl_xor_sync(0xffffffffu, p0, off);
            p1 += __shfl_xor_sync(0xffffffffu, p1, off);
        }
        if (lane == 0) {
            float l0 = p0 + fcb[0], l1 = p1 + fcb[1];
            float mx = fmaxf(l0, l1);
            float lse = mx + logf(expf(l0 - mx) + expf(l1 - mx));
            out[(size_t)warp * 2]     = l0 - lse;
            out[(size_t)warp * 2 + 1] = l1 - lse;
        }
    }
}

// ---------------- launch ----------------------------------------------------------
extern "C" void kernel_launch(void* const* d_in, const int* in_sizes, int n_in,
                              void* d_out, int out_size) {
    const float* x   = (const float*)d_in[0];
    const void*  ei  = d_in[1];
    const float* ea  = (const float*)d_in[2];
    const float* g[3]  = {(const float*)d_in[3],  (const float*)d_in[8],  (const float*)d_in[13]};
    const float* mu[3] = {(const float*)d_in[4],  (const float*)d_in[9],  (const float*)d_in[14]};
    const float* sg[3] = {(const float*)d_in[5],  (const float*)d_in[10], (const float*)d_in[15]};
    const float* rt[3] = {(const float*)d_in[6],  (const float*)d_in[11], (const float*)d_in[16]};
    const float* bi[3] = {(const float*)d_in[7],  (const float*)d_in[12], (const float*)d_in[17]};
    const float* fcw = (const float*)d_in[18];
    const float* fcb = (const float*)d_in[19];
    float* out = (float*)d_out;

    float *xwm, *xwr, *h0, *h1;
    cudaGetSymbolAddress((void**)&xwm, d_xwm);
    cudaGetSymbolAddress((void**)&xwr, d_xwr);
    cudaGetSymbolAddress((void**)&h0,  d_h0);
    cudaGetSymbolAddress((void**)&h1,  d_h1);

    const int EB = (N_EDGES + 255) / 256;
    const int NB = (N_NODES + 255) / 256;
    const int GW = (N_NODES * 32 + 255) / 256;   // warp-per-node grids

    // ---- CSR build (shared by all 3 layers) ----
    detect_kernel<<<1, 32>>>((const unsigned*)ei);
    convert_edges<<<EB, 256>>>(ei);
    zero_cnt<<<NB, 256>>>();
    hist_kernel<<<EB, 256>>>();
    scan1<<<SCAN_NB, SCAN_B>>>();
    scan2<<<1, 32>>>();
    scan3<<<NB, 256>>>();
    fill_kernel<<<EB, 256>>>(ea);

    // ---- layer 0: 22 -> 32 ----
    gauss_csr<<<EB, 256>>>(mu[0], sg[0]);
    gemm_s<22, 32, 32, 4, 4, 16><<<(N_NODES + 15) / 16, dim3(32, 4)>>>(x, g[0], rt[0], xwm, xwr);
    gather32<<<GW, 256>>>(xwm, xwr, bi[0], h0);

    // ---- layer 1: 32 -> 64 ----
    gauss_csr<<<EB, 256>>>(mu[1], sg[1]);
    gemm_vec<32, 32, 4><<<(N_NODES + 31) / 32, dim3(32, 8)>>>(h0, g[1], rt[1], xwm, xwr);
    gather64<false><<<GW, 256>>>(xwm, xwr, bi[1], fcw, fcb, h1);

    // ---- layer 2: 64 -> 64 (fused FC + log_softmax) ----
    gauss_csr<<<EB, 256>>>(mu[2], sg[2]);
    gemm_vec<64, 32, 4><<<(N_NODES + 31) / 32, dim3(32, 8)>>>(h1, g[2], rt[2], xwm, xwr);
    gather64<true><<<GW, 256>>>(xwm, xwr, bi[2], fcw, fcb, out);
}